// round 9
// baseline (speedup 1.0000x reference)
#include <cuda_runtime.h>
#include <cuda_bf16.h>
#include <cstdint>

#define L 6400
#define C 256
#define HW 80
#define MARG 2
#define THRESH 0.2f
// sim = dot / (C * 0.1f)
#define SCALE (1.0f / 25.6f)

// ---------------- device scratch (no allocations allowed) ----------------
__device__ __nv_bfloat16 g_A[L * C];
__device__ __nv_bfloat16 g_B[L * C];
__device__ float g_E[(size_t)L * L];          // exp(sim), 164 MB
__device__ float g_rowsum[L];
__device__ float g_colsum[L];
__device__ float g_invrs[L];
__device__ float g_invcs[L];
__device__ unsigned g_rowmax[L];              // conf row max as float bits (conf > 0)
__device__ unsigned g_colmax[L];

// conf must be computed bit-identically in k_max and k_final
__device__ __forceinline__ float conf_fn(float e, float irs, float ics) {
    return __fmul_rn(__fmul_rn(e, irs), __fmul_rn(e, ics));
}

__device__ __forceinline__ bool interior(int idx) {
    int i0 = idx / HW;
    int j0 = idx - i0 * HW;
    return ((unsigned)(i0 - MARG) < (unsigned)(HW - 2 * MARG)) &&
           ((unsigned)(j0 - MARG) < (unsigned)(HW - 2 * MARG));
}

// ---------------- fp32 -> bf16 conversion ----------------
__global__ void k_convert(const float* __restrict__ x0, const float* __restrict__ x1) {
    int i = blockIdx.x * blockDim.x + threadIdx.x;   // over L*C/4
    if (i >= L * C / 4) return;
    float4 a = ((const float4*)x0)[i];
    float4 b = ((const float4*)x1)[i];
    __nv_bfloat162* oa = (__nv_bfloat162*)g_A;
    __nv_bfloat162* ob = (__nv_bfloat162*)g_B;
    oa[2 * i + 0] = __floats2bfloat162_rn(a.x, a.y);
    oa[2 * i + 1] = __floats2bfloat162_rn(a.z, a.w);
    ob[2 * i + 0] = __floats2bfloat162_rn(b.x, b.y);
    ob[2 * i + 1] = __floats2bfloat162_rn(b.z, b.w);
}

__global__ void k_init() {
    int i = blockIdx.x * blockDim.x + threadIdx.x;
    if (i < L) {
        g_rowsum[i] = 0.f;
        g_colsum[i] = 0.f;
        g_rowmax[i] = 0u;   // bits of +0.0f; conf > 0 always
        g_colmax[i] = 0u;
    }
}

// ---------------- GEMM: E = exp(scale * x0 @ x1^T) ----------------
#define BM 128
#define BN 128
#define BK 32
#define PADK 40   // rows stride 80B -> conflict-free ldmatrix

__global__ void __launch_bounds__(256) k_gemm() {
    __shared__ __align__(16) __nv_bfloat16 As[BM * PADK];
    __shared__ __align__(16) __nv_bfloat16 Bs[BN * PADK];

    const int tid  = threadIdx.x;
    const int lane = tid & 31;
    const int wid  = tid >> 5;
    const int wm   = wid >> 2;   // 0..1  (64 rows each)
    const int wn   = wid & 3;    // 0..3  (32 cols each)
    const int m0   = blockIdx.y * BM;
    const int n0   = blockIdx.x * BN;

    float acc[4][4][4];
#pragma unroll
    for (int mi = 0; mi < 4; mi++)
#pragma unroll
        for (int ni = 0; ni < 4; ni++)
#pragma unroll
            for (int j = 0; j < 4; j++) acc[mi][ni][j] = 0.f;

    const uint32_t as_base = (uint32_t)__cvta_generic_to_shared(As);
    const uint32_t bs_base = (uint32_t)__cvta_generic_to_shared(Bs);

    for (int kb = 0; kb < C; kb += BK) {
        // global -> smem: 128 rows x 32 bf16 (4x uint4 per row), 512 uint4, 2 per thread
#pragma unroll
        for (int t = 0; t < 2; t++) {
            int idx = tid + t * 256;
            int row = idx >> 2;
            int ch  = idx & 3;
            const uint4* sa = (const uint4*)(g_A + (size_t)(m0 + row) * C + kb + ch * 8);
            const uint4* sb = (const uint4*)(g_B + (size_t)(n0 + row) * C + kb + ch * 8);
            *(uint4*)(As + row * PADK + ch * 8) = *sa;
            *(uint4*)(Bs + row * PADK + ch * 8) = *sb;
        }
        __syncthreads();

#pragma unroll
        for (int kk = 0; kk < 2; kk++) {
            const int k16 = kk * 16;
            uint32_t a[4][4], b[4][2];
#pragma unroll
            for (int mi = 0; mi < 4; mi++) {
                int mrow = wm * 64 + mi * 16 + (lane & 15);
                int kcol = k16 + ((lane >> 4) << 3);
                uint32_t addr = as_base + (uint32_t)(mrow * PADK + kcol) * 2u;
                asm volatile(
                    "ldmatrix.sync.aligned.m8n8.x4.shared.b16 {%0,%1,%2,%3},[%4];"
                    : "=r"(a[mi][0]), "=r"(a[mi][1]), "=r"(a[mi][2]), "=r"(a[mi][3])
                    : "r"(addr));
            }
#pragma unroll
            for (int ni = 0; ni < 4; ni++) {
                int l    = lane & 15;
                int nrow = wn * 32 + ni * 8 + (l & 7);
                int kcol = k16 + ((l >> 3) << 3);
                uint32_t addr = bs_base + (uint32_t)(nrow * PADK + kcol) * 2u;
                asm volatile(
                    "ldmatrix.sync.aligned.m8n8.x2.shared.b16 {%0,%1},[%2];"
                    : "=r"(b[ni][0]), "=r"(b[ni][1])
                    : "r"(addr));
            }
#pragma unroll
            for (int mi = 0; mi < 4; mi++)
#pragma unroll
                for (int ni = 0; ni < 4; ni++) {
                    asm volatile(
                        "mma.sync.aligned.m16n8k16.row.col.f32.bf16.bf16.f32 "
                        "{%0,%1,%2,%3},{%4,%5,%6,%7},{%8,%9},{%0,%1,%2,%3};"
                        : "+f"(acc[mi][ni][0]), "+f"(acc[mi][ni][1]),
                          "+f"(acc[mi][ni][2]), "+f"(acc[mi][ni][3])
                        : "r"(a[mi][0]), "r"(a[mi][1]), "r"(a[mi][2]), "r"(a[mi][3]),
                          "r"(b[ni][0]), "r"(b[ni][1]));
                }
        }
        __syncthreads();
    }

    // epilogue: E = exp(acc * SCALE)
    const int qr = lane >> 2;
    const int qc = lane & 3;
#pragma unroll
    for (int mi = 0; mi < 4; mi++) {
        int gr = m0 + wm * 64 + mi * 16 + qr;
#pragma unroll
        for (int ni = 0; ni < 4; ni++) {
            int gc = n0 + wn * 32 + ni * 8 + qc * 2;
            float e0 = __expf(acc[mi][ni][0] * SCALE);
            float e1 = __expf(acc[mi][ni][1] * SCALE);
            float e2 = __expf(acc[mi][ni][2] * SCALE);
            float e3 = __expf(acc[mi][ni][3] * SCALE);
            *(float2*)&g_E[(size_t)gr * L + gc]       = make_float2(e0, e1);
            *(float2*)&g_E[(size_t)(gr + 8) * L + gc] = make_float2(e2, e3);
        }
    }
}

// ---------------- pass 2: row & col sums of E ----------------
__global__ void __launch_bounds__(256) k_sums() {
    const int tid = threadIdx.x, lane = tid & 31, w = tid >> 5;
    const int r0 = blockIdx.y * 128, c0 = blockIdx.x * 128;
    const int c = c0 + lane * 4;

    __shared__ float scol[128];
    if (tid < 128) scol[tid] = 0.f;
    __syncthreads();

    float cs0 = 0.f, cs1 = 0.f, cs2 = 0.f, cs3 = 0.f;
#pragma unroll 4
    for (int i = 0; i < 16; i++) {
        int r = r0 + w + i * 8;
        float4 v = *(const float4*)&g_E[(size_t)r * L + c];
        cs0 += v.x; cs1 += v.y; cs2 += v.z; cs3 += v.w;
        float p = (v.x + v.y) + (v.z + v.w);
#pragma unroll
        for (int o = 16; o; o >>= 1) p += __shfl_xor_sync(0xffffffffu, p, o);
        if (lane == 0) atomicAdd(&g_rowsum[r], p);
    }
    atomicAdd(&scol[lane * 4 + 0], cs0);
    atomicAdd(&scol[lane * 4 + 1], cs1);
    atomicAdd(&scol[lane * 4 + 2], cs2);
    atomicAdd(&scol[lane * 4 + 3], cs3);
    __syncthreads();
    if (tid < 128) atomicAdd(&g_colsum[c0 + tid], scol[tid]);
}

__global__ void k_recip() {
    int i = blockIdx.x * blockDim.x + threadIdx.x;
    if (i < L) {
        g_invrs[i] = 1.0f / g_rowsum[i];
        g_invcs[i] = 1.0f / g_colsum[i];
    }
}

// ---------------- pass 3: row & col maxima of conf ----------------
__global__ void __launch_bounds__(256) k_max() {
    const int tid = threadIdx.x, lane = tid & 31, w = tid >> 5;
    const int r0 = blockIdx.y * 128, c0 = blockIdx.x * 128;
    const int c = c0 + lane * 4;

    const float ics0 = g_invcs[c + 0], ics1 = g_invcs[c + 1];
    const float ics2 = g_invcs[c + 2], ics3 = g_invcs[c + 3];

    __shared__ unsigned smax[128];
    if (tid < 128) smax[tid] = 0u;
    __syncthreads();

    float cm0 = 0.f, cm1 = 0.f, cm2 = 0.f, cm3 = 0.f;
#pragma unroll 4
    for (int i = 0; i < 16; i++) {
        int r = r0 + w + i * 8;
        float irs = g_invrs[r];
        float4 v = *(const float4*)&g_E[(size_t)r * L + c];
        float f0 = conf_fn(v.x, irs, ics0);
        float f1 = conf_fn(v.y, irs, ics1);
        float f2 = conf_fn(v.z, irs, ics2);
        float f3 = conf_fn(v.w, irs, ics3);
        cm0 = fmaxf(cm0, f0); cm1 = fmaxf(cm1, f1);
        cm2 = fmaxf(cm2, f2); cm3 = fmaxf(cm3, f3);
        float p = fmaxf(fmaxf(f0, f1), fmaxf(f2, f3));
#pragma unroll
        for (int o = 16; o; o >>= 1) p = fmaxf(p, __shfl_xor_sync(0xffffffffu, p, o));
        if (lane == 0) atomicMax(&g_rowmax[r], __float_as_uint(p));
    }
    atomicMax(&smax[lane * 4 + 0], __float_as_uint(cm0));
    atomicMax(&smax[lane * 4 + 1], __float_as_uint(cm1));
    atomicMax(&smax[lane * 4 + 2], __float_as_uint(cm2));
    atomicMax(&smax[lane * 4 + 3], __float_as_uint(cm3));
    __syncthreads();
    if (tid < 128) atomicMax(&g_colmax[c0 + tid], smax[tid]);
}

// ---------------- pass 4: masked output ----------------
__global__ void __launch_bounds__(256) k_final(float* __restrict__ out) {
    const int tid = threadIdx.x, lane = tid & 31, w = tid >> 5;
    const int r0 = blockIdx.y * 128, c0 = blockIdx.x * 128;
    const int c = c0 + lane * 4;

    const float ics0 = g_invcs[c + 0], ics1 = g_invcs[c + 1];
    const float ics2 = g_invcs[c + 2], ics3 = g_invcs[c + 3];
    const unsigned cb0 = g_colmax[c + 0], cb1 = g_colmax[c + 1];
    const unsigned cb2 = g_colmax[c + 2], cb3 = g_colmax[c + 3];
    const bool cv0 = interior(c + 0), cv1 = interior(c + 1);
    const bool cv2 = interior(c + 2), cv3 = interior(c + 3);

#pragma unroll 4
    for (int i = 0; i < 16; i++) {
        int r = r0 + w + i * 8;
        float irs = g_invrs[r];
        unsigned rb = g_rowmax[r];
        bool rv = interior(r);
        float4 v = *(const float4*)&g_E[(size_t)r * L + c];
        float f0 = conf_fn(v.x, irs, ics0);
        float f1 = conf_fn(v.y, irs, ics1);
        float f2 = conf_fn(v.z, irs, ics2);
        float f3 = conf_fn(v.w, irs, ics3);
        float4 o;
        o.x = (rv && cv0 && f0 > THRESH && __float_as_uint(f0) == rb && __float_as_uint(f0) == cb0) ? f0 : 0.f;
        o.y = (rv && cv1 && f1 > THRESH && __float_as_uint(f1) == rb && __float_as_uint(f1) == cb1) ? f1 : 0.f;
        o.z = (rv && cv2 && f2 > THRESH && __float_as_uint(f2) == rb && __float_as_uint(f2) == cb2) ? f2 : 0.f;
        o.w = (rv && cv3 && f3 > THRESH && __float_as_uint(f3) == rb && __float_as_uint(f3) == cb3) ? f3 : 0.f;
        *(float4*)&out[(size_t)r * L + c] = o;
    }
}

// ---------------- launch ----------------
extern "C" void kernel_launch(void* const* d_in, const int* in_sizes, int n_in,
                              void* d_out, int out_size) {
    const float* x0 = (const float*)d_in[0];
    const float* x1 = (const float*)d_in[1];
    float* out = (float*)d_out;

    k_convert<<<(L * C / 4 + 255) / 256, 256>>>(x0, x1);
    k_init<<<(L + 255) / 256, 256>>>();

    dim3 grid(L / BN, L / BM);   // 50 x 50
    k_gemm<<<grid, 256>>>();
    k_sums<<<grid, 256>>>();
    k_recip<<<(L + 255) / 256, 256>>>();
    k_max<<<grid, 256>>>();
    k_final<<<grid, 256>>>(out);
}

// round 10
// speedup vs baseline: 1.4205x; 1.4205x over previous
#include <cuda_runtime.h>
#include <cuda_bf16.h>
#include <cstdint>

#define L 6400
#define C 256
#define HW 80
#define MARG 2
#define THRESH 0.2f
// sim = dot / (C * 0.1f)
#define SCALE (1.0f / 25.6f)
#define CAND_MAX 65536

// ---------------- device scratch (no allocations allowed) ----------------
__device__ __nv_bfloat16 g_A[L * C];
__device__ __nv_bfloat16 g_B[L * C];
__device__ __nv_bfloat16 g_Ebf[(size_t)L * L];   // exp(sim) in bf16, 82 MB
__device__ float g_rowsum[L];
__device__ float g_colsum[L];
__device__ float g_invrs[L];
__device__ float g_invcs[L];
__device__ unsigned g_rowmax[L];                 // conf row max as float bits (conf > 0)
__device__ unsigned g_colmax[L];
__device__ int g_ncand;
__device__ uint4 g_cand[CAND_MAX];               // {row, col, conf_bits, pad}

// conf must be computed bit-identically in k_maxcand (-> rowmax/colmax/candidates)
__device__ __forceinline__ float conf_fn(float e, float irs, float ics) {
    return __fmul_rn(__fmul_rn(e, irs), __fmul_rn(e, ics));
}

__device__ __forceinline__ bool interior(int idx) {
    int i0 = idx / HW;
    int j0 = idx - i0 * HW;
    return ((unsigned)(i0 - MARG) < (unsigned)(HW - 2 * MARG)) &&
           ((unsigned)(j0 - MARG) < (unsigned)(HW - 2 * MARG));
}

// ---------------- fp32 -> bf16 conversion ----------------
__global__ void k_convert(const float* __restrict__ x0, const float* __restrict__ x1) {
    int i = blockIdx.x * blockDim.x + threadIdx.x;   // over L*C/4
    if (i >= L * C / 4) return;
    float4 a = ((const float4*)x0)[i];
    float4 b = ((const float4*)x1)[i];
    __nv_bfloat162* oa = (__nv_bfloat162*)g_A;
    __nv_bfloat162* ob = (__nv_bfloat162*)g_B;
    oa[2 * i + 0] = __floats2bfloat162_rn(a.x, a.y);
    oa[2 * i + 1] = __floats2bfloat162_rn(a.z, a.w);
    ob[2 * i + 0] = __floats2bfloat162_rn(b.x, b.y);
    ob[2 * i + 1] = __floats2bfloat162_rn(b.z, b.w);
}

__global__ void k_init() {
    int i = blockIdx.x * blockDim.x + threadIdx.x;
    if (i < L) {
        g_rowsum[i] = 0.f;
        g_colsum[i] = 0.f;
        g_rowmax[i] = 0u;   // bits of +0.0f; conf > 0 always
        g_colmax[i] = 0u;
    }
    if (i == 0) g_ncand = 0;
}

// ---------------- GEMM: E = exp(scale * x0 @ x1^T) + fused row/col sums ----------------
#define BM 128
#define BN 128
#define BK 32
#define PADK 40   // rows stride 80B -> conflict-free ldmatrix, cp.async dst stays 16B aligned

__global__ void __launch_bounds__(256) k_gemm() {
    __shared__ __align__(16) __nv_bfloat16 As[2][BM * PADK];
    __shared__ __align__(16) __nv_bfloat16 Bs[2][BN * PADK];
    __shared__ float srow[BM];
    __shared__ float scol[BN];

    const int tid  = threadIdx.x;
    const int lane = tid & 31;
    const int wid  = tid >> 5;
    const int wm   = wid >> 2;   // 0..1  (64 rows each)
    const int wn   = wid & 3;    // 0..3  (32 cols each)
    const int m0   = blockIdx.y * BM;
    const int n0   = blockIdx.x * BN;

    if (tid < BM) { srow[tid] = 0.f; scol[tid] = 0.f; }

    float acc[4][4][4];
#pragma unroll
    for (int mi = 0; mi < 4; mi++)
#pragma unroll
        for (int ni = 0; ni < 4; ni++)
#pragma unroll
            for (int j = 0; j < 4; j++) acc[mi][ni][j] = 0.f;

    const uint32_t as0 = (uint32_t)__cvta_generic_to_shared(&As[0][0]);
    const uint32_t bs0 = (uint32_t)__cvta_generic_to_shared(&Bs[0][0]);
    const uint32_t stage_bytes = (uint32_t)(BM * PADK * 2);

    // cp.async prefetch of one BK-slab into stage s
    auto prefetch = [&](int kb, int s) {
#pragma unroll
        for (int t = 0; t < 2; t++) {
            int idx = tid + t * 256;
            int row = idx >> 2;
            int ch  = idx & 3;
            uint32_t off = (uint32_t)s * stage_bytes + (uint32_t)(row * PADK + ch * 8) * 2u;
            const void* sa = (const void*)(g_A + (size_t)(m0 + row) * C + kb + ch * 8);
            const void* sb = (const void*)(g_B + (size_t)(n0 + row) * C + kb + ch * 8);
            asm volatile("cp.async.cg.shared.global [%0],[%1],16;\n" :: "r"(as0 + off), "l"(sa));
            asm volatile("cp.async.cg.shared.global [%0],[%1],16;\n" :: "r"(bs0 + off), "l"(sb));
        }
    };

    prefetch(0, 0);
    asm volatile("cp.async.commit_group;\n");

    int s = 0;
    for (int kbi = 0; kbi < C / BK; kbi++) {
        if (kbi + 1 < C / BK) {
            prefetch((kbi + 1) * BK, s ^ 1);
            asm volatile("cp.async.commit_group;\n");
            asm volatile("cp.async.wait_group 1;\n");
        } else {
            asm volatile("cp.async.wait_group 0;\n");
        }
        __syncthreads();

        const uint32_t as_base = as0 + (uint32_t)s * stage_bytes;
        const uint32_t bs_base = bs0 + (uint32_t)s * stage_bytes;
#pragma unroll
        for (int kk = 0; kk < 2; kk++) {
            const int k16 = kk * 16;
            uint32_t a[4][4], b[4][2];
#pragma unroll
            for (int mi = 0; mi < 4; mi++) {
                int mrow = wm * 64 + mi * 16 + (lane & 15);
                int kcol = k16 + ((lane >> 4) << 3);
                uint32_t addr = as_base + (uint32_t)(mrow * PADK + kcol) * 2u;
                asm volatile(
                    "ldmatrix.sync.aligned.m8n8.x4.shared.b16 {%0,%1,%2,%3},[%4];"
                    : "=r"(a[mi][0]), "=r"(a[mi][1]), "=r"(a[mi][2]), "=r"(a[mi][3])
                    : "r"(addr));
            }
#pragma unroll
            for (int ni = 0; ni < 4; ni++) {
                int l    = lane & 15;
                int nrow = wn * 32 + ni * 8 + (l & 7);
                int kcol = k16 + ((l >> 3) << 3);
                uint32_t addr = bs_base + (uint32_t)(nrow * PADK + kcol) * 2u;
                asm volatile(
                    "ldmatrix.sync.aligned.m8n8.x2.shared.b16 {%0,%1},[%2];"
                    : "=r"(b[ni][0]), "=r"(b[ni][1])
                    : "r"(addr));
            }
#pragma unroll
            for (int mi = 0; mi < 4; mi++)
#pragma unroll
                for (int ni = 0; ni < 4; ni++) {
                    asm volatile(
                        "mma.sync.aligned.m16n8k16.row.col.f32.bf16.bf16.f32 "
                        "{%0,%1,%2,%3},{%4,%5,%6,%7},{%8,%9},{%0,%1,%2,%3};"
                        : "+f"(acc[mi][ni][0]), "+f"(acc[mi][ni][1]),
                          "+f"(acc[mi][ni][2]), "+f"(acc[mi][ni][3])
                        : "r"(a[mi][0]), "r"(a[mi][1]), "r"(a[mi][2]), "r"(a[mi][3]),
                          "r"(b[ni][0]), "r"(b[ni][1]));
                }
        }
        __syncthreads();
        s ^= 1;
    }

    // epilogue: E = exp(acc * SCALE), store bf16, fused row/col partial sums
    const int qr = lane >> 2;
    const int qc = lane & 3;
    float rowp[4][2];
    float colp[4][2];
#pragma unroll
    for (int i = 0; i < 4; i++) { rowp[i][0] = rowp[i][1] = 0.f; colp[i][0] = colp[i][1] = 0.f; }

#pragma unroll
    for (int mi = 0; mi < 4; mi++) {
        int gr = m0 + wm * 64 + mi * 16 + qr;
#pragma unroll
        for (int ni = 0; ni < 4; ni++) {
            int gc = n0 + wn * 32 + ni * 8 + qc * 2;
            float e0 = __expf(acc[mi][ni][0] * SCALE);
            float e1 = __expf(acc[mi][ni][1] * SCALE);
            float e2 = __expf(acc[mi][ni][2] * SCALE);
            float e3 = __expf(acc[mi][ni][3] * SCALE);
            *(__nv_bfloat162*)&g_Ebf[(size_t)gr * L + gc]       = __floats2bfloat162_rn(e0, e1);
            *(__nv_bfloat162*)&g_Ebf[(size_t)(gr + 8) * L + gc] = __floats2bfloat162_rn(e2, e3);
            rowp[mi][0] += e0 + e1;
            rowp[mi][1] += e2 + e3;
            colp[ni][0] += e0 + e2;
            colp[ni][1] += e1 + e3;
        }
    }

    // row partials: reduce across qc lanes (xor 1,2), lane qc==0 owns the row
#pragma unroll
    for (int mi = 0; mi < 4; mi++) {
#pragma unroll
        for (int h = 0; h < 2; h++) {
            float p = rowp[mi][h];
            p += __shfl_xor_sync(0xffffffffu, p, 1);
            p += __shfl_xor_sync(0xffffffffu, p, 2);
            if (qc == 0) atomicAdd(&srow[wm * 64 + mi * 16 + qr + h * 8], p);
        }
    }
    // col partials: reduce across qr lanes (xor 4,8,16), lane qr==0 owns the col
#pragma unroll
    for (int ni = 0; ni < 4; ni++) {
#pragma unroll
        for (int h = 0; h < 2; h++) {
            float p = colp[ni][h];
            p += __shfl_xor_sync(0xffffffffu, p, 4);
            p += __shfl_xor_sync(0xffffffffu, p, 8);
            p += __shfl_xor_sync(0xffffffffu, p, 16);
            if (qr == 0) atomicAdd(&scol[wn * 32 + ni * 8 + qc * 2 + h], p);
        }
    }
    __syncthreads();
    if (tid < BM) {
        atomicAdd(&g_rowsum[m0 + tid], srow[tid]);
        atomicAdd(&g_colsum[n0 + tid], scol[tid]);
    }
}

__global__ void k_recip() {
    int i = blockIdx.x * blockDim.x + threadIdx.x;
    if (i < L) {
        g_invrs[i] = 1.0f / g_rowsum[i];
        g_invcs[i] = 1.0f / g_colsum[i];
    }
}

// ---------------- pass 2: conf maxima + candidate capture (read-only over E) ----------------
__global__ void __launch_bounds__(256) k_maxcand() {
    const int tid = threadIdx.x, lane = tid & 31, w = tid >> 5;
    const int r0 = blockIdx.y * 128, c0 = blockIdx.x * 128;
    const int c = c0 + lane * 4;

    const float ics0 = g_invcs[c + 0], ics1 = g_invcs[c + 1];
    const float ics2 = g_invcs[c + 2], ics3 = g_invcs[c + 3];

    __shared__ unsigned smax[128];
    if (tid < 128) smax[tid] = 0u;
    __syncthreads();

    float cm0 = 0.f, cm1 = 0.f, cm2 = 0.f, cm3 = 0.f;
#pragma unroll 4
    for (int i = 0; i < 16; i++) {
        int r = r0 + w + i * 8;
        float irs = g_invrs[r];
        uint2 raw = *(const uint2*)&g_Ebf[(size_t)r * L + c];
        __nv_bfloat162 p01 = *(__nv_bfloat162*)&raw.x;
        __nv_bfloat162 p23 = *(__nv_bfloat162*)&raw.y;
        float f0 = conf_fn(__bfloat162float(p01.x), irs, ics0);
        float f1 = conf_fn(__bfloat162float(p01.y), irs, ics1);
        float f2 = conf_fn(__bfloat162float(p23.x), irs, ics2);
        float f3 = conf_fn(__bfloat162float(p23.y), irs, ics3);
        cm0 = fmaxf(cm0, f0); cm1 = fmaxf(cm1, f1);
        cm2 = fmaxf(cm2, f2); cm3 = fmaxf(cm3, f3);

        float p = fmaxf(fmaxf(f0, f1), fmaxf(f2, f3));
#pragma unroll
        for (int o = 16; o; o >>= 1) p = fmaxf(p, __shfl_xor_sync(0xffffffffu, p, o));
        if (lane == 0) atomicMax(&g_rowmax[r], __float_as_uint(p));

        // candidate capture: structurally ~never taken (conf ~ 2e-5 << 0.2)
        if (f0 > THRESH) { int ix = atomicAdd(&g_ncand, 1); if (ix < CAND_MAX) g_cand[ix] = make_uint4(r, c + 0, __float_as_uint(f0), 0); }
        if (f1 > THRESH) { int ix = atomicAdd(&g_ncand, 1); if (ix < CAND_MAX) g_cand[ix] = make_uint4(r, c + 1, __float_as_uint(f1), 0); }
        if (f2 > THRESH) { int ix = atomicAdd(&g_ncand, 1); if (ix < CAND_MAX) g_cand[ix] = make_uint4(r, c + 2, __float_as_uint(f2), 0); }
        if (f3 > THRESH) { int ix = atomicAdd(&g_ncand, 1); if (ix < CAND_MAX) g_cand[ix] = make_uint4(r, c + 3, __float_as_uint(f3), 0); }
    }
    atomicMax(&smax[lane * 4 + 0], __float_as_uint(cm0));
    atomicMax(&smax[lane * 4 + 1], __float_as_uint(cm1));
    atomicMax(&smax[lane * 4 + 2], __float_as_uint(cm2));
    atomicMax(&smax[lane * 4 + 3], __float_as_uint(cm3));
    __syncthreads();
    if (tid < 128) atomicMax(&g_colmax[c0 + tid], smax[tid]);
}

// ---------------- pass 3: resolve candidates, write sparse nonzeros ----------------
__global__ void k_fixup(float* __restrict__ out) {
    int n = g_ncand;
    if (n > CAND_MAX) n = CAND_MAX;
    for (int i = blockIdx.x * blockDim.x + threadIdx.x; i < n; i += gridDim.x * blockDim.x) {
        uint4 cd = g_cand[i];
        int r = (int)cd.x, c = (int)cd.y;
        unsigned bits = cd.z;
        if (interior(r) && interior(c) &&
            bits == g_rowmax[r] && bits == g_colmax[c]) {
            out[(size_t)r * L + c] = __uint_as_float(bits);
        }
    }
}

// ---------------- launch ----------------
extern "C" void kernel_launch(void* const* d_in, const int* in_sizes, int n_in,
                              void* d_out, int out_size) {
    const float* x0 = (const float*)d_in[0];
    const float* x1 = (const float*)d_in[1];
    float* out = (float*)d_out;

    cudaMemsetAsync(d_out, 0, (size_t)out_size * sizeof(float), 0);
    k_convert<<<(L * C / 4 + 255) / 256, 256>>>(x0, x1);
    k_init<<<(L + 255) / 256, 256>>>();

    dim3 grid(L / BN, L / BM);   // 50 x 50
    k_gemm<<<grid, 256>>>();
    k_recip<<<(L + 255) / 256, 256>>>();
    k_maxcand<<<grid, 256>>>();
    k_fixup<<<32, 256>>>(out);
}

// round 11
// speedup vs baseline: 1.4241x; 1.0025x over previous
#include <cuda_runtime.h>
#include <cuda_bf16.h>
#include <cstdint>

#define L 6400
#define C 256
#define HW 80
#define MARG 2
#define THRESH 0.2f
// sim = dot / (C * 0.1f)
#define SCALE (1.0f / 25.6f)
#define CAND_MAX 65536

// ---------------- device scratch (no allocations allowed) ----------------
__device__ __nv_bfloat16 g_A[L * C];
__device__ __nv_bfloat16 g_B[L * C];
__device__ __nv_bfloat16 g_Ebf[(size_t)L * L];   // exp(sim) in bf16, 82 MB
__device__ float g_rowsum[L];
__device__ float g_colsum[L];
__device__ float g_invrs[L];
__device__ float g_invcs[L];
__device__ unsigned g_rowmax[L];                 // conf row max as float bits (conf > 0)
__device__ unsigned g_colmax[L];
__device__ int g_ncand;
__device__ uint4 g_cand[CAND_MAX];               // {row, col, conf_bits, pad}

// conf must be computed bit-identically in k_maxcand (-> rowmax/colmax/candidates)
__device__ __forceinline__ float conf_fn(float e, float irs, float ics) {
    return __fmul_rn(__fmul_rn(e, irs), __fmul_rn(e, ics));
}

__device__ __forceinline__ bool interior(int idx) {
    int i0 = idx / HW;
    int j0 = idx - i0 * HW;
    return ((unsigned)(i0 - MARG) < (unsigned)(HW - 2 * MARG)) &&
           ((unsigned)(j0 - MARG) < (unsigned)(HW - 2 * MARG));
}

// ---------------- fp32 -> bf16 conversion ----------------
__global__ void k_convert(const float* __restrict__ x0, const float* __restrict__ x1) {
    int i = blockIdx.x * blockDim.x + threadIdx.x;   // over L*C/4
    if (i >= L * C / 4) return;
    float4 a = ((const float4*)x0)[i];
    float4 b = ((const float4*)x1)[i];
    __nv_bfloat162* oa = (__nv_bfloat162*)g_A;
    __nv_bfloat162* ob = (__nv_bfloat162*)g_B;
    oa[2 * i + 0] = __floats2bfloat162_rn(a.x, a.y);
    oa[2 * i + 1] = __floats2bfloat162_rn(a.z, a.w);
    ob[2 * i + 0] = __floats2bfloat162_rn(b.x, b.y);
    ob[2 * i + 1] = __floats2bfloat162_rn(b.z, b.w);
}

__global__ void k_init() {
    int i = blockIdx.x * blockDim.x + threadIdx.x;
    if (i < L) {
        g_rowsum[i] = 0.f;
        g_colsum[i] = 0.f;
        g_rowmax[i] = 0u;   // bits of +0.0f; conf > 0 always
        g_colmax[i] = 0u;
    }
    if (i == 0) g_ncand = 0;
}

// ---------------- GEMM: E = exp(scale * x0 @ x1^T) + fused row/col sums ----------------
#define BM 128
#define BN 128
#define BK 32
#define PADK 40   // rows stride 80B -> conflict-free ldmatrix, cp.async dst stays 16B aligned

__global__ void __launch_bounds__(256) k_gemm() {
    __shared__ __align__(16) __nv_bfloat16 As[2][BM * PADK];
    __shared__ __align__(16) __nv_bfloat16 Bs[2][BN * PADK];
    __shared__ float srow[BM];
    __shared__ float scol[BN];

    const int tid  = threadIdx.x;
    const int lane = tid & 31;
    const int wid  = tid >> 5;
    const int wm   = wid >> 2;   // 0..1  (64 rows each)
    const int wn   = wid & 3;    // 0..3  (32 cols each)
    const int m0   = blockIdx.y * BM;
    const int n0   = blockIdx.x * BN;

    if (tid < BM) { srow[tid] = 0.f; scol[tid] = 0.f; }

    float acc[4][4][4];
#pragma unroll
    for (int mi = 0; mi < 4; mi++)
#pragma unroll
        for (int ni = 0; ni < 4; ni++)
#pragma unroll
            for (int j = 0; j < 4; j++) acc[mi][ni][j] = 0.f;

    const uint32_t as0 = (uint32_t)__cvta_generic_to_shared(&As[0][0]);
    const uint32_t bs0 = (uint32_t)__cvta_generic_to_shared(&Bs[0][0]);
    const uint32_t stage_bytes = (uint32_t)(BM * PADK * 2);

    // cp.async prefetch of one BK-slab into stage s
    auto prefetch = [&](int kb, int s) {
#pragma unroll
        for (int t = 0; t < 2; t++) {
            int idx = tid + t * 256;
            int row = idx >> 2;
            int ch  = idx & 3;
            uint32_t off = (uint32_t)s * stage_bytes + (uint32_t)(row * PADK + ch * 8) * 2u;
            const void* sa = (const void*)(g_A + (size_t)(m0 + row) * C + kb + ch * 8);
            const void* sb = (const void*)(g_B + (size_t)(n0 + row) * C + kb + ch * 8);
            asm volatile("cp.async.cg.shared.global [%0],[%1],16;\n" :: "r"(as0 + off), "l"(sa));
            asm volatile("cp.async.cg.shared.global [%0],[%1],16;\n" :: "r"(bs0 + off), "l"(sb));
        }
    };

    prefetch(0, 0);
    asm volatile("cp.async.commit_group;\n");

    int s = 0;
    for (int kbi = 0; kbi < C / BK; kbi++) {
        if (kbi + 1 < C / BK) {
            prefetch((kbi + 1) * BK, s ^ 1);
            asm volatile("cp.async.commit_group;\n");
            asm volatile("cp.async.wait_group 1;\n");
        } else {
            asm volatile("cp.async.wait_group 0;\n");
        }
        __syncthreads();

        const uint32_t as_base = as0 + (uint32_t)s * stage_bytes;
        const uint32_t bs_base = bs0 + (uint32_t)s * stage_bytes;
#pragma unroll
        for (int kk = 0; kk < 2; kk++) {
            const int k16 = kk * 16;
            uint32_t a[4][4], b[4][2];
#pragma unroll
            for (int mi = 0; mi < 4; mi++) {
                int mrow = wm * 64 + mi * 16 + (lane & 15);
                int kcol = k16 + ((lane >> 4) << 3);
                uint32_t addr = as_base + (uint32_t)(mrow * PADK + kcol) * 2u;
                asm volatile(
                    "ldmatrix.sync.aligned.m8n8.x4.shared.b16 {%0,%1,%2,%3},[%4];"
                    : "=r"(a[mi][0]), "=r"(a[mi][1]), "=r"(a[mi][2]), "=r"(a[mi][3])
                    : "r"(addr));
            }
#pragma unroll
            for (int ni = 0; ni < 4; ni++) {
                int l    = lane & 15;
                int nrow = wn * 32 + ni * 8 + (l & 7);
                int kcol = k16 + ((l >> 3) << 3);
                uint32_t addr = bs_base + (uint32_t)(nrow * PADK + kcol) * 2u;
                asm volatile(
                    "ldmatrix.sync.aligned.m8n8.x2.shared.b16 {%0,%1},[%2];"
                    : "=r"(b[ni][0]), "=r"(b[ni][1])
                    : "r"(addr));
            }
#pragma unroll
            for (int mi = 0; mi < 4; mi++)
#pragma unroll
                for (int ni = 0; ni < 4; ni++) {
                    asm volatile(
                        "mma.sync.aligned.m16n8k16.row.col.f32.bf16.bf16.f32 "
                        "{%0,%1,%2,%3},{%4,%5,%6,%7},{%8,%9},{%0,%1,%2,%3};"
                        : "+f"(acc[mi][ni][0]), "+f"(acc[mi][ni][1]),
                          "+f"(acc[mi][ni][2]), "+f"(acc[mi][ni][3])
                        : "r"(a[mi][0]), "r"(a[mi][1]), "r"(a[mi][2]), "r"(a[mi][3]),
                          "r"(b[ni][0]), "r"(b[ni][1]));
                }
        }
        __syncthreads();
        s ^= 1;
    }

    // epilogue: E = exp(acc * SCALE), store bf16, fused row/col partial sums
    const int qr = lane >> 2;
    const int qc = lane & 3;
    float rowp[4][2];
    float colp[4][2];
#pragma unroll
    for (int i = 0; i < 4; i++) { rowp[i][0] = rowp[i][1] = 0.f; colp[i][0] = colp[i][1] = 0.f; }

#pragma unroll
    for (int mi = 0; mi < 4; mi++) {
        int gr = m0 + wm * 64 + mi * 16 + qr;
#pragma unroll
        for (int ni = 0; ni < 4; ni++) {
            int gc = n0 + wn * 32 + ni * 8 + qc * 2;
            float e0 = __expf(acc[mi][ni][0] * SCALE);
            float e1 = __expf(acc[mi][ni][1] * SCALE);
            float e2 = __expf(acc[mi][ni][2] * SCALE);
            float e3 = __expf(acc[mi][ni][3] * SCALE);
            *(__nv_bfloat162*)&g_Ebf[(size_t)gr * L + gc]       = __floats2bfloat162_rn(e0, e1);
            *(__nv_bfloat162*)&g_Ebf[(size_t)(gr + 8) * L + gc] = __floats2bfloat162_rn(e2, e3);
            rowp[mi][0] += e0 + e1;
            rowp[mi][1] += e2 + e3;
            colp[ni][0] += e0 + e2;
            colp[ni][1] += e1 + e3;
        }
    }

    // row partials: reduce across qc lanes (xor 1,2), lane qc==0 owns the row
#pragma unroll
    for (int mi = 0; mi < 4; mi++) {
#pragma unroll
        for (int h = 0; h < 2; h++) {
            float p = rowp[mi][h];
            p += __shfl_xor_sync(0xffffffffu, p, 1);
            p += __shfl_xor_sync(0xffffffffu, p, 2);
            if (qc == 0) atomicAdd(&srow[wm * 64 + mi * 16 + qr + h * 8], p);
        }
    }
    // col partials: reduce across qr lanes (xor 4,8,16), lane qr==0 owns the col
#pragma unroll
    for (int ni = 0; ni < 4; ni++) {
#pragma unroll
        for (int h = 0; h < 2; h++) {
            float p = colp[ni][h];
            p += __shfl_xor_sync(0xffffffffu, p, 4);
            p += __shfl_xor_sync(0xffffffffu, p, 8);
            p += __shfl_xor_sync(0xffffffffu, p, 16);
            if (qr == 0) atomicAdd(&scol[wn * 32 + ni * 8 + qc * 2 + h], p);
        }
    }
    __syncthreads();
    if (tid < BM) {
        atomicAdd(&g_rowsum[m0 + tid], srow[tid]);
        atomicAdd(&g_colsum[n0 + tid], scol[tid]);
    }
}

__global__ void k_recip() {
    int i = blockIdx.x * blockDim.x + threadIdx.x;
    if (i < L) {
        g_invrs[i] = 1.0f / g_rowsum[i];
        g_invcs[i] = 1.0f / g_colsum[i];
    }
}

// ---------------- pass 2: conf maxima + candidate capture (read-only over E) ----------------
__global__ void __launch_bounds__(256) k_maxcand() {
    const int tid = threadIdx.x, lane = tid & 31, w = tid >> 5;
    const int r0 = blockIdx.y * 128, c0 = blockIdx.x * 128;
    const int c = c0 + lane * 4;

    const float ics0 = g_invcs[c + 0], ics1 = g_invcs[c + 1];
    const float ics2 = g_invcs[c + 2], ics3 = g_invcs[c + 3];

    __shared__ unsigned smax[128];
    if (tid < 128) smax[tid] = 0u;
    __syncthreads();

    float cm0 = 0.f, cm1 = 0.f, cm2 = 0.f, cm3 = 0.f;
#pragma unroll 4
    for (int i = 0; i < 16; i++) {
        int r = r0 + w + i * 8;
        float irs = g_invrs[r];
        uint2 raw = *(const uint2*)&g_Ebf[(size_t)r * L + c];
        __nv_bfloat162 p01 = *(__nv_bfloat162*)&raw.x;
        __nv_bfloat162 p23 = *(__nv_bfloat162*)&raw.y;
        float f0 = conf_fn(__bfloat162float(p01.x), irs, ics0);
        float f1 = conf_fn(__bfloat162float(p01.y), irs, ics1);
        float f2 = conf_fn(__bfloat162float(p23.x), irs, ics2);
        float f3 = conf_fn(__bfloat162float(p23.y), irs, ics3);
        cm0 = fmaxf(cm0, f0); cm1 = fmaxf(cm1, f1);
        cm2 = fmaxf(cm2, f2); cm3 = fmaxf(cm3, f3);

        float p = fmaxf(fmaxf(f0, f1), fmaxf(f2, f3));
#pragma unroll
        for (int o = 16; o; o >>= 1) p = fmaxf(p, __shfl_xor_sync(0xffffffffu, p, o));
        if (lane == 0) atomicMax(&g_rowmax[r], __float_as_uint(p));

        // candidate capture: structurally ~never taken (conf ~ 2e-5 << 0.2)
        if (f0 > THRESH) { int ix = atomicAdd(&g_ncand, 1); if (ix < CAND_MAX) g_cand[ix] = make_uint4(r, c + 0, __float_as_uint(f0), 0); }
        if (f1 > THRESH) { int ix = atomicAdd(&g_ncand, 1); if (ix < CAND_MAX) g_cand[ix] = make_uint4(r, c + 1, __float_as_uint(f1), 0); }
        if (f2 > THRESH) { int ix = atomicAdd(&g_ncand, 1); if (ix < CAND_MAX) g_cand[ix] = make_uint4(r, c + 2, __float_as_uint(f2), 0); }
        if (f3 > THRESH) { int ix = atomicAdd(&g_ncand, 1); if (ix < CAND_MAX) g_cand[ix] = make_uint4(r, c + 3, __float_as_uint(f3), 0); }
    }
    atomicMax(&smax[lane * 4 + 0], __float_as_uint(cm0));
    atomicMax(&smax[lane * 4 + 1], __float_as_uint(cm1));
    atomicMax(&smax[lane * 4 + 2], __float_as_uint(cm2));
    atomicMax(&smax[lane * 4 + 3], __float_as_uint(cm3));
    __syncthreads();
    if (tid < 128) atomicMax(&g_colmax[c0 + tid], smax[tid]);
}

// ---------------- pass 3: resolve candidates, write sparse nonzeros ----------------
__global__ void k_fixup(float* __restrict__ out) {
    int n = g_ncand;
    if (n > CAND_MAX) n = CAND_MAX;
    for (int i = blockIdx.x * blockDim.x + threadIdx.x; i < n; i += gridDim.x * blockDim.x) {
        uint4 cd = g_cand[i];
        int r = (int)cd.x, c = (int)cd.y;
        unsigned bits = cd.z;
        if (interior(r) && interior(c) &&
            bits == g_rowmax[r] && bits == g_colmax[c]) {
            out[(size_t)r * L + c] = __uint_as_float(bits);
        }
    }
}

// ---------------- launch ----------------
extern "C" void kernel_launch(void* const* d_in, const int* in_sizes, int n_in,
                              void* d_out, int out_size) {
    const float* x0 = (const float*)d_in[0];
    const float* x1 = (const float*)d_in[1];
    float* out = (float*)d_out;

    cudaMemsetAsync(d_out, 0, (size_t)out_size * sizeof(float), 0);
    k_convert<<<(L * C / 4 + 255) / 256, 256>>>(x0, x1);
    k_init<<<(L + 255) / 256, 256>>>();

    dim3 grid(L / BN, L / BM);   // 50 x 50
    k_gemm<<<grid, 256>>>();
    k_recip<<<(L + 255) / 256, 256>>>();
    k_maxcand<<<grid, 256>>>();
    k_fixup<<<32, 256>>>(out);
}

// round 12
// speedup vs baseline: 1.7221x; 1.2093x over previous
#include <cuda_runtime.h>
#include <cuda_bf16.h>
#include <cstdint>

#define L 6400
#define C 256
#define HW 80
#define MARG 2
#define THRESH 0.2f
// sim = dot / (C * 0.1f)
#define SCALE (1.0f / 25.6f)
#define CAND_MAX 65536

// ---------------- device scratch (no allocations allowed) ----------------
__device__ __nv_bfloat16 g_A[L * C];
__device__ __nv_bfloat16 g_B[L * C];
__device__ __nv_bfloat16 g_Ebf[(size_t)L * L];   // exp(sim) in bf16, 82 MB
__device__ float g_rowsum[L];
__device__ float g_colsum[L];
__device__ float g_invrs[L];
__device__ float g_invcs[L];
__device__ int g_ncand;
__device__ uint4 g_cand[CAND_MAX];               // {row, col, conf_bits, pad}

// conf must be computed bit-identically in k_scan and k_resolve
__device__ __forceinline__ float conf_fn(float e, float irs, float ics) {
    return __fmul_rn(__fmul_rn(e, irs), __fmul_rn(e, ics));
}

__device__ __forceinline__ bool interior(int idx) {
    int i0 = idx / HW;
    int j0 = idx - i0 * HW;
    return ((unsigned)(i0 - MARG) < (unsigned)(HW - 2 * MARG)) &&
           ((unsigned)(j0 - MARG) < (unsigned)(HW - 2 * MARG));
}

// ---------------- fp32 -> bf16 conversion (+ init of small arrays) ----------------
__global__ void k_convert(const float* __restrict__ x0, const float* __restrict__ x1) {
    int i = blockIdx.x * blockDim.x + threadIdx.x;   // over L*C/4
    if (i < L) {
        g_rowsum[i] = 0.f;
        g_colsum[i] = 0.f;
    }
    if (i == 0) g_ncand = 0;
    if (i >= L * C / 4) return;
    float4 a = ((const float4*)x0)[i];
    float4 b = ((const float4*)x1)[i];
    __nv_bfloat162* oa = (__nv_bfloat162*)g_A;
    __nv_bfloat162* ob = (__nv_bfloat162*)g_B;
    oa[2 * i + 0] = __floats2bfloat162_rn(a.x, a.y);
    oa[2 * i + 1] = __floats2bfloat162_rn(a.z, a.w);
    ob[2 * i + 0] = __floats2bfloat162_rn(b.x, b.y);
    ob[2 * i + 1] = __floats2bfloat162_rn(b.z, b.w);
}

// ---------------- GEMM: E = exp(scale * x0 @ x1^T) + fused row/col sums ----------------
#define BM 128
#define BN 128
#define BK 32
#define PADK 40    // mainloop rows stride 80B -> conflict-free ldmatrix
#define PADC 136   // epilogue conf tile stride (272B -> bank shift 4/row, conflict-free)

#define STAGE_B (BM * PADK * 2)       // bytes per operand per stage (10240)
#define SMEM_MAIN (4 * STAGE_B)       // As[2] + Bs[2] = 40960 B (>= 128*PADC*2 = 34816 B)

__global__ void __launch_bounds__(256) k_gemm() {
    __shared__ __align__(16) char sm_raw[SMEM_MAIN];
    __shared__ float srow[BM];
    __shared__ float scol[BN];

    const int tid  = threadIdx.x;
    const int lane = tid & 31;
    const int wid  = tid >> 5;
    const int wm   = wid >> 2;   // 0..1  (64 rows each)
    const int wn   = wid & 3;    // 0..3  (32 cols each)
    const int m0   = blockIdx.y * BM;
    const int n0   = blockIdx.x * BN;

    if (tid < BM) { srow[tid] = 0.f; scol[tid] = 0.f; }

    float acc[4][4][4];
#pragma unroll
    for (int mi = 0; mi < 4; mi++)
#pragma unroll
        for (int ni = 0; ni < 4; ni++)
#pragma unroll
            for (int j = 0; j < 4; j++) acc[mi][ni][j] = 0.f;

    const uint32_t base = (uint32_t)__cvta_generic_to_shared(sm_raw);
    // layout: [As s0][As s1][Bs s0][Bs s1]
    auto as_of = [&](int s) { return base + (uint32_t)s * STAGE_B; };
    auto bs_of = [&](int s) { return base + 2u * STAGE_B + (uint32_t)s * STAGE_B; };

    auto prefetch = [&](int kb, int s) {
#pragma unroll
        for (int t = 0; t < 2; t++) {
            int idx = tid + t * 256;
            int row = idx >> 2;
            int ch  = idx & 3;
            uint32_t off = (uint32_t)(row * PADK + ch * 8) * 2u;
            const void* sa = (const void*)(g_A + (size_t)(m0 + row) * C + kb + ch * 8);
            const void* sb = (const void*)(g_B + (size_t)(n0 + row) * C + kb + ch * 8);
            asm volatile("cp.async.cg.shared.global [%0],[%1],16;\n" :: "r"(as_of(s) + off), "l"(sa));
            asm volatile("cp.async.cg.shared.global [%0],[%1],16;\n" :: "r"(bs_of(s) + off), "l"(sb));
        }
    };

    prefetch(0, 0);
    asm volatile("cp.async.commit_group;\n");

    int s = 0;
    for (int kbi = 0; kbi < C / BK; kbi++) {
        if (kbi + 1 < C / BK) {
            prefetch((kbi + 1) * BK, s ^ 1);
            asm volatile("cp.async.commit_group;\n");
            asm volatile("cp.async.wait_group 1;\n");
        } else {
            asm volatile("cp.async.wait_group 0;\n");
        }
        __syncthreads();

        const uint32_t as_base = as_of(s);
        const uint32_t bs_base = bs_of(s);
#pragma unroll
        for (int kk = 0; kk < 2; kk++) {
            const int k16 = kk * 16;
            uint32_t a[4][4], b[4][2];
#pragma unroll
            for (int mi = 0; mi < 4; mi++) {
                int mrow = wm * 64 + mi * 16 + (lane & 15);
                int kcol = k16 + ((lane >> 4) << 3);
                uint32_t addr = as_base + (uint32_t)(mrow * PADK + kcol) * 2u;
                asm volatile(
                    "ldmatrix.sync.aligned.m8n8.x4.shared.b16 {%0,%1,%2,%3},[%4];"
                    : "=r"(a[mi][0]), "=r"(a[mi][1]), "=r"(a[mi][2]), "=r"(a[mi][3])
                    : "r"(addr));
            }
            // B: two x4 ldmatrix, each covering an (ni, ni+1) pair x (klo, khi)
#pragma unroll
            for (int p = 0; p < 2; p++) {
                int g  = lane >> 3;      // matrix index 0..3
                int lr = lane & 7;
                int nrow = wn * 32 + (2 * p + (g >> 1)) * 8 + lr;
                int kcol = k16 + (g & 1) * 8;
                uint32_t addr = bs_base + (uint32_t)(nrow * PADK + kcol) * 2u;
                asm volatile(
                    "ldmatrix.sync.aligned.m8n8.x4.shared.b16 {%0,%1,%2,%3},[%4];"
                    : "=r"(b[2 * p][0]), "=r"(b[2 * p][1]),
                      "=r"(b[2 * p + 1][0]), "=r"(b[2 * p + 1][1])
                    : "r"(addr));
            }
#pragma unroll
            for (int mi = 0; mi < 4; mi++)
#pragma unroll
                for (int ni = 0; ni < 4; ni++) {
                    asm volatile(
                        "mma.sync.aligned.m16n8k16.row.col.f32.bf16.bf16.f32 "
                        "{%0,%1,%2,%3},{%4,%5,%6,%7},{%8,%9},{%0,%1,%2,%3};"
                        : "+f"(acc[mi][ni][0]), "+f"(acc[mi][ni][1]),
                          "+f"(acc[mi][ni][2]), "+f"(acc[mi][ni][3])
                        : "r"(a[mi][0]), "r"(a[mi][1]), "r"(a[mi][2]), "r"(a[mi][3]),
                          "r"(b[ni][0]), "r"(b[ni][1]));
                }
        }
        __syncthreads();
        s ^= 1;
    }

    // ---- epilogue: exp, fused row/col sums, stage conf tile in smem, coalesced store ----
    __nv_bfloat16* Cs = (__nv_bfloat16*)sm_raw;   // 128 x PADC bf16 (mainloop smem done)
    const int qr = lane >> 2;
    const int qc = lane & 3;
    float rowp[4][2];
    float colp[4][2];
#pragma unroll
    for (int i = 0; i < 4; i++) { rowp[i][0] = rowp[i][1] = 0.f; colp[i][0] = colp[i][1] = 0.f; }

#pragma unroll
    for (int mi = 0; mi < 4; mi++) {
        int lr = wm * 64 + mi * 16 + qr;
#pragma unroll
        for (int ni = 0; ni < 4; ni++) {
            int lc = wn * 32 + ni * 8 + qc * 2;
            float e0 = __expf(acc[mi][ni][0] * SCALE);
            float e1 = __expf(acc[mi][ni][1] * SCALE);
            float e2 = __expf(acc[mi][ni][2] * SCALE);
            float e3 = __expf(acc[mi][ni][3] * SCALE);
            *(__nv_bfloat162*)&Cs[lr * PADC + lc]       = __floats2bfloat162_rn(e0, e1);
            *(__nv_bfloat162*)&Cs[(lr + 8) * PADC + lc] = __floats2bfloat162_rn(e2, e3);
            rowp[mi][0] += e0 + e1;
            rowp[mi][1] += e2 + e3;
            colp[ni][0] += e0 + e2;
            colp[ni][1] += e1 + e3;
        }
    }

    // row partials: reduce across qc lanes (xor 1,2)
#pragma unroll
    for (int mi = 0; mi < 4; mi++)
#pragma unroll
        for (int h = 0; h < 2; h++) {
            float p = rowp[mi][h];
            p += __shfl_xor_sync(0xffffffffu, p, 1);
            p += __shfl_xor_sync(0xffffffffu, p, 2);
            if (qc == 0) atomicAdd(&srow[wm * 64 + mi * 16 + qr + h * 8], p);
        }
    // col partials: reduce across qr lanes (xor 4,8,16)
#pragma unroll
    for (int ni = 0; ni < 4; ni++)
#pragma unroll
        for (int h = 0; h < 2; h++) {
            float p = colp[ni][h];
            p += __shfl_xor_sync(0xffffffffu, p, 4);
            p += __shfl_xor_sync(0xffffffffu, p, 8);
            p += __shfl_xor_sync(0xffffffffu, p, 16);
            if (qr == 0) atomicAdd(&scol[wn * 32 + ni * 8 + qc * 2 + h], p);
        }
    __syncthreads();
    if (tid < BM) {
        atomicAdd(&g_rowsum[m0 + tid], srow[tid]);
        atomicAdd(&g_colsum[n0 + tid], scol[tid]);
    }

    // coalesced tile store: half-warp per row, 16B per lane
    const int row16 = tid >> 4;    // 0..15
    const int l16   = tid & 15;
#pragma unroll
    for (int it = 0; it < 8; it++) {
        int row = it * 16 + row16;
        uint4 v = *(uint4*)&Cs[row * PADC + l16 * 8];
        *(uint4*)&g_Ebf[(size_t)(m0 + row) * L + n0 + l16 * 8] = v;
    }
}

__global__ void k_recip() {
    int i = blockIdx.x * blockDim.x + threadIdx.x;
    if (i < L) {
        g_invrs[i] = 1.0f / g_rowsum[i];
        g_invcs[i] = 1.0f / g_colsum[i];
    }
}

// ---------------- pass 2: zero output + candidate capture (read-only over E) ----------------
__global__ void __launch_bounds__(256) k_scan(float* __restrict__ out) {
    const int tid = threadIdx.x, lane = tid & 31, w = tid >> 5;
    const int r0 = blockIdx.y * 128, c0 = blockIdx.x * 128;
    const int c = c0 + lane * 4;

    const float ics0 = g_invcs[c + 0], ics1 = g_invcs[c + 1];
    const float ics2 = g_invcs[c + 2], ics3 = g_invcs[c + 3];
    const float4 zero = make_float4(0.f, 0.f, 0.f, 0.f);

#pragma unroll 4
    for (int i = 0; i < 16; i++) {
        int r = r0 + w + i * 8;
        float irs = g_invrs[r];
        uint2 raw = *(const uint2*)&g_Ebf[(size_t)r * L + c];
        __nv_bfloat162 p01 = *(__nv_bfloat162*)&raw.x;
        __nv_bfloat162 p23 = *(__nv_bfloat162*)&raw.y;
        float f0 = conf_fn(__bfloat162float(p01.x), irs, ics0);
        float f1 = conf_fn(__bfloat162float(p01.y), irs, ics1);
        float f2 = conf_fn(__bfloat162float(p23.x), irs, ics2);
        float f3 = conf_fn(__bfloat162float(p23.y), irs, ics3);
        // candidates: structurally ~never taken (conf ~ 2e-5 << 0.2)
        if (fmaxf(fmaxf(f0, f1), fmaxf(f2, f3)) > THRESH) {
            if (f0 > THRESH) { int ix = atomicAdd(&g_ncand, 1); if (ix < CAND_MAX) g_cand[ix] = make_uint4(r, c + 0, __float_as_uint(f0), 0); }
            if (f1 > THRESH) { int ix = atomicAdd(&g_ncand, 1); if (ix < CAND_MAX) g_cand[ix] = make_uint4(r, c + 1, __float_as_uint(f1), 0); }
            if (f2 > THRESH) { int ix = atomicAdd(&g_ncand, 1); if (ix < CAND_MAX) g_cand[ix] = make_uint4(r, c + 2, __float_as_uint(f2), 0); }
            if (f3 > THRESH) { int ix = atomicAdd(&g_ncand, 1); if (ix < CAND_MAX) g_cand[ix] = make_uint4(r, c + 3, __float_as_uint(f3), 0); }
        }
        *(float4*)&out[(size_t)r * L + c] = zero;
    }
}

// ---------------- pass 3: per-candidate row/col max, write sparse nonzeros ----------------
__global__ void __launch_bounds__(256) k_resolve(float* __restrict__ out) {
    __shared__ float sred[2][8];
    int n = g_ncand;
    if (n > CAND_MAX) n = CAND_MAX;
    const int tid = threadIdx.x, lane = tid & 31, w = tid >> 5;

    for (int ci = blockIdx.x; ci < n; ci += gridDim.x) {
        uint4 cd = g_cand[ci];
        int r = (int)cd.x, c = (int)cd.y;
        unsigned bits = cd.z;
        float irs = g_invrs[r];
        float ics = g_invcs[c];

        float rm = 0.f, cm = 0.f;
        for (int j = tid; j < L; j += 256) {
            rm = fmaxf(rm, conf_fn(__bfloat162float(g_Ebf[(size_t)r * L + j]), irs, g_invcs[j]));
            cm = fmaxf(cm, conf_fn(__bfloat162float(g_Ebf[(size_t)j * L + c]), g_invrs[j], ics));
        }
#pragma unroll
        for (int o = 16; o; o >>= 1) {
            rm = fmaxf(rm, __shfl_xor_sync(0xffffffffu, rm, o));
            cm = fmaxf(cm, __shfl_xor_sync(0xffffffffu, cm, o));
        }
        if (lane == 0) { sred[0][w] = rm; sred[1][w] = cm; }
        __syncthreads();
        if (tid == 0) {
            float rmax = sred[0][0], cmax = sred[1][0];
#pragma unroll
            for (int k = 1; k < 8; k++) {
                rmax = fmaxf(rmax, sred[0][k]);
                cmax = fmaxf(cmax, sred[1][k]);
            }
            if (bits == __float_as_uint(rmax) && bits == __float_as_uint(cmax) &&
                interior(r) && interior(c)) {
                out[(size_t)r * L + c] = __uint_as_float(bits);
            }
        }
        __syncthreads();
    }
}

// ---------------- launch ----------------
extern "C" void kernel_launch(void* const* d_in, const int* in_sizes, int n_in,
                              void* d_out, int out_size) {
    const float* x0 = (const float*)d_in[0];
    const float* x1 = (const float*)d_in[1];
    float* out = (float*)d_out;

    k_convert<<<(L * C / 4 + 255) / 256, 256>>>(x0, x1);

    dim3 grid(L / BN, L / BM);   // 50 x 50
    k_gemm<<<grid, 256>>>();
    k_recip<<<(L + 255) / 256, 256>>>();
    k_scan<<<grid, 256>>>(out);
    k_resolve<<<64, 256>>>(out);
}

// round 13
// speedup vs baseline: 1.8151x; 1.0540x over previous
#include <cuda_runtime.h>
#include <cuda_bf16.h>
#include <cuda_fp8.h>
#include <cstdint>

#define L 6400
#define C 256
#define HW 80
#define MARG 2
#define THRESH 0.2f
// sim = dot / (C * 0.1f)
#define SCALE (1.0f / 25.6f)
#define CAND_MAX 65536

// ---------------- device scratch (no allocations allowed) ----------------
__device__ uint8_t g_A8[L * C];                  // fp8 e4m3 copies
__device__ uint8_t g_B8[L * C];
__device__ __nv_bfloat16 g_Ebf[(size_t)L * L];   // exp(sim) bf16 — written ONLY on fallback
__device__ float g_rowsum[L];
__device__ float g_colsum[L];
__device__ float g_invrs[L];
__device__ float g_invcs[L];
__device__ unsigned g_rsmin;                     // positive-float bits, atomicMin
__device__ unsigned g_csmin;
__device__ unsigned g_simmax_key;                // order-encoded float, atomicMax
__device__ int g_flag;                           // 1 -> candidates possible (fallback)
__device__ int g_ncand;
__device__ uint4 g_cand[CAND_MAX];               // {row, col, conf_bits, pad}

// conf computed bit-identically in fallback-capture and resolve
__device__ __forceinline__ float conf_fn(float e, float irs, float ics) {
    return __fmul_rn(__fmul_rn(e, irs), __fmul_rn(e, ics));
}

__device__ __forceinline__ bool interior(int idx) {
    int i0 = idx / HW;
    int j0 = idx - i0 * HW;
    return ((unsigned)(i0 - MARG) < (unsigned)(HW - 2 * MARG)) &&
           ((unsigned)(j0 - MARG) < (unsigned)(HW - 2 * MARG));
}

// monotone float<->uint encoding (handles negatives) for atomicMax
__device__ __forceinline__ unsigned enc_f(float f) {
    unsigned b = __float_as_uint(f);
    return b ^ ((unsigned)((int)b >> 31) | 0x80000000u);
}
__device__ __forceinline__ float dec_f(unsigned k) {
    unsigned b = (k & 0x80000000u) ? (k ^ 0x80000000u) : ~k;
    return __uint_as_float(b);
}

// ---------------- fp32 -> fp8 conversion (+ init) ----------------
__global__ void k_convert(const float* __restrict__ x0, const float* __restrict__ x1) {
    int i = blockIdx.x * blockDim.x + threadIdx.x;   // over L*C/4
    if (i < L) { g_rowsum[i] = 0.f; g_colsum[i] = 0.f; }
    if (i == 0) {
        g_ncand = 0;
        g_rsmin = 0x7F800000u;   // +inf bits
        g_csmin = 0x7F800000u;
        g_simmax_key = 0u;
    }
    if (i >= L * C / 4) return;
    float4 a = ((const float4*)x0)[i];
    float4 b = ((const float4*)x1)[i];
    unsigned pa = (unsigned)__nv_cvt_float2_to_fp8x2(make_float2(a.x, a.y), __NV_SATFINITE, __NV_E4M3)
                | ((unsigned)__nv_cvt_float2_to_fp8x2(make_float2(a.z, a.w), __NV_SATFINITE, __NV_E4M3) << 16);
    unsigned pb = (unsigned)__nv_cvt_float2_to_fp8x2(make_float2(b.x, b.y), __NV_SATFINITE, __NV_E4M3)
                | ((unsigned)__nv_cvt_float2_to_fp8x2(make_float2(b.z, b.w), __NV_SATFINITE, __NV_E4M3) << 16);
    ((unsigned*)g_A8)[i] = pa;
    ((unsigned*)g_B8)[i] = pb;
}

// ---------------- shared fp8 GEMM mainloop (BM=BN=128, BK=64 bytes) ----------------
#define BM 128
#define BN 128
#define BKB 64      // k-bytes per stage
#define PADB 80     // row stride in bytes (16B aligned, conflict-free ldmatrix)
#define STAGE_B (BM * PADB)            // 10240 B
#define SMEM_MAIN (4 * STAGE_B)        // As[2] + Bs[2] = 40 KB

// computes acc[4][4][4] for this warp's 64x... tile partition
#define GEMM_MAINLOOP(ACC)                                                              \
    {                                                                                   \
        auto as_of = [&](int s_) { return base + (uint32_t)s_ * STAGE_B; };             \
        auto bs_of = [&](int s_) { return base + 2u * STAGE_B + (uint32_t)s_ * STAGE_B; };\
        auto prefetch = [&](int kb, int s_) {                                           \
            _Pragma("unroll")                                                           \
            for (int t = 0; t < 2; t++) {                                               \
                int idx = tid + t * 256;                                                \
                int row = idx >> 2;                                                     \
                int ch  = idx & 3;                                                      \
                uint32_t off = (uint32_t)(row * PADB + ch * 16);                        \
                const void* sa = (const void*)(g_A8 + (size_t)(m0 + row) * C + kb + ch * 16);\
                const void* sb = (const void*)(g_B8 + (size_t)(n0 + row) * C + kb + ch * 16);\
                asm volatile("cp.async.cg.shared.global [%0],[%1],16;\n" :: "r"(as_of(s_) + off), "l"(sa));\
                asm volatile("cp.async.cg.shared.global [%0],[%1],16;\n" :: "r"(bs_of(s_) + off), "l"(sb));\
            }                                                                           \
        };                                                                              \
        prefetch(0, 0);                                                                 \
        asm volatile("cp.async.commit_group;\n");                                       \
        int s = 0;                                                                      \
        for (int kbi = 0; kbi < C / BKB; kbi++) {                                       \
            if (kbi + 1 < C / BKB) {                                                    \
                prefetch((kbi + 1) * BKB, s ^ 1);                                       \
                asm volatile("cp.async.commit_group;\n");                               \
                asm volatile("cp.async.wait_group 1;\n");                               \
            } else {                                                                    \
                asm volatile("cp.async.wait_group 0;\n");                               \
            }                                                                           \
            __syncthreads();                                                            \
            const uint32_t as_base = as_of(s);                                          \
            const uint32_t bs_base = bs_of(s);                                          \
            _Pragma("unroll")                                                           \
            for (int kk = 0; kk < 2; kk++) {                                            \
                uint32_t a[4][4], b[4][2];                                              \
                _Pragma("unroll")                                                       \
                for (int mi = 0; mi < 4; mi++) {                                        \
                    int mrow = wm * 64 + mi * 16 + (lane & 15);                         \
                    int kcol = kk * 32 + ((lane >> 4) << 4);                            \
                    uint32_t addr = as_base + (uint32_t)(mrow * PADB + kcol);           \
                    asm volatile(                                                       \
                        "ldmatrix.sync.aligned.m8n8.x4.shared.b16 {%0,%1,%2,%3},[%4];"  \
                        : "=r"(a[mi][0]), "=r"(a[mi][1]), "=r"(a[mi][2]), "=r"(a[mi][3])\
                        : "r"(addr));                                                   \
                }                                                                       \
                _Pragma("unroll")                                                       \
                for (int p = 0; p < 2; p++) {                                           \
                    int g  = lane >> 3;                                                 \
                    int lr = lane & 7;                                                  \
                    int nrow = wn * 32 + (2 * p + (g >> 1)) * 8 + lr;                   \
                    int kcol = kk * 32 + (g & 1) * 16;                                  \
                    uint32_t addr = bs_base + (uint32_t)(nrow * PADB + kcol);           \
                    asm volatile(                                                       \
                        "ldmatrix.sync.aligned.m8n8.x4.shared.b16 {%0,%1,%2,%3},[%4];"  \
                        : "=r"(b[2 * p][0]), "=r"(b[2 * p][1]),                         \
                          "=r"(b[2 * p + 1][0]), "=r"(b[2 * p + 1][1])                  \
                        : "r"(addr));                                                   \
                }                                                                       \
                _Pragma("unroll")                                                       \
                for (int mi = 0; mi < 4; mi++)                                          \
                    _Pragma("unroll")                                                   \
                    for (int ni = 0; ni < 4; ni++) {                                    \
                        asm volatile(                                                   \
                            "mma.sync.aligned.m16n8k32.row.col.f32.e4m3.e4m3.f32 "      \
                            "{%0,%1,%2,%3},{%4,%5,%6,%7},{%8,%9},{%0,%1,%2,%3};"        \
                            : "+f"(ACC[mi][ni][0]), "+f"(ACC[mi][ni][1]),               \
                              "+f"(ACC[mi][ni][2]), "+f"(ACC[mi][ni][3])                \
                            : "r"(a[mi][0]), "r"(a[mi][1]), "r"(a[mi][2]), "r"(a[mi][3]),\
                              "r"(b[ni][0]), "r"(b[ni][1]));                            \
                    }                                                                   \
            }                                                                           \
            __syncthreads();                                                            \
            s ^= 1;                                                                     \
        }                                                                               \
    }

// ---------------- pass 1: stats GEMM (rowsum/colsum of e, global max sim) ----------------
__global__ void __launch_bounds__(256) k_gemm_stats() {
    __shared__ __align__(16) char sm_raw[SMEM_MAIN];
    __shared__ float srow[BM];
    __shared__ float scol[BN];

    const int tid  = threadIdx.x;
    const int lane = tid & 31;
    const int wid  = tid >> 5;
    const int wm   = wid >> 2;
    const int wn   = wid & 3;
    const int m0   = blockIdx.y * BM;
    const int n0   = blockIdx.x * BN;
    const uint32_t base = (uint32_t)__cvta_generic_to_shared(sm_raw);

    if (tid < BM) { srow[tid] = 0.f; scol[tid] = 0.f; }

    float acc[4][4][4];
#pragma unroll
    for (int mi = 0; mi < 4; mi++)
#pragma unroll
        for (int ni = 0; ni < 4; ni++)
#pragma unroll
            for (int j = 0; j < 4; j++) acc[mi][ni][j] = 0.f;

    GEMM_MAINLOOP(acc)

    // epilogue: e = exp(acc*SCALE); fused row/col sums; global max of sim
    const int qr = lane >> 2;
    const int qc = lane & 3;
    float rowp[4][2], colp[4][2];
#pragma unroll
    for (int i = 0; i < 4; i++) { rowp[i][0] = rowp[i][1] = 0.f; colp[i][0] = colp[i][1] = 0.f; }
    float amax = -1e30f;

#pragma unroll
    for (int mi = 0; mi < 4; mi++) {
#pragma unroll
        for (int ni = 0; ni < 4; ni++) {
            float a0 = acc[mi][ni][0], a1 = acc[mi][ni][1];
            float a2 = acc[mi][ni][2], a3 = acc[mi][ni][3];
            amax = fmaxf(amax, fmaxf(fmaxf(a0, a1), fmaxf(a2, a3)));
            float e0 = __expf(a0 * SCALE);
            float e1 = __expf(a1 * SCALE);
            float e2 = __expf(a2 * SCALE);
            float e3 = __expf(a3 * SCALE);
            rowp[mi][0] += e0 + e1;
            rowp[mi][1] += e2 + e3;
            colp[ni][0] += e0 + e2;
            colp[ni][1] += e1 + e3;
        }
    }
#pragma unroll
    for (int o = 16; o; o >>= 1) amax = fmaxf(amax, __shfl_xor_sync(0xffffffffu, amax, o));
    if (lane == 0) atomicMax(&g_simmax_key, enc_f(amax * SCALE));

#pragma unroll
    for (int mi = 0; mi < 4; mi++)
#pragma unroll
        for (int h = 0; h < 2; h++) {
            float p = rowp[mi][h];
            p += __shfl_xor_sync(0xffffffffu, p, 1);
            p += __shfl_xor_sync(0xffffffffu, p, 2);
            if (qc == 0) atomicAdd(&srow[wm * 64 + mi * 16 + qr + h * 8], p);
        }
#pragma unroll
    for (int ni = 0; ni < 4; ni++)
#pragma unroll
        for (int h = 0; h < 2; h++) {
            float p = colp[ni][h];
            p += __shfl_xor_sync(0xffffffffu, p, 4);
            p += __shfl_xor_sync(0xffffffffu, p, 8);
            p += __shfl_xor_sync(0xffffffffu, p, 16);
            if (qr == 0) atomicAdd(&scol[wn * 32 + ni * 8 + qc * 2 + h], p);
        }
    __syncthreads();
    if (tid < BM) {
        atomicAdd(&g_rowsum[m0 + tid], srow[tid]);
        atomicAdd(&g_colsum[n0 + tid], scol[tid]);
    }
}

// ---------------- recip + global mins ----------------
__global__ void k_post() {
    int i = blockIdx.x * blockDim.x + threadIdx.x;
    if (i < L) {
        float rs = g_rowsum[i], cs = g_colsum[i];
        g_invrs[i] = 1.0f / rs;
        g_invcs[i] = 1.0f / cs;
        atomicMin(&g_rsmin, __float_as_uint(rs));   // positive floats: uint order == float order
        atomicMin(&g_csmin, __float_as_uint(cs));
    }
}

// ---------------- screening flag ----------------
__global__ void k_flag() {
    if (threadIdx.x == 0) {
        float smax  = dec_f(g_simmax_key);
        float rsmin = __uint_as_float(g_rsmin);
        float csmin = __uint_as_float(g_csmin);
        // conf <= exp(2*smax)/(rsmin*csmin); 2.0-nat margin covers fp8/bf16/fp32 discrepancy
        g_flag = (2.f * smax - __logf(rsmin) - __logf(csmin) >= __logf(THRESH) - 2.0f) ? 1 : 0;
    }
}

// ---------------- pass 2: zero output; gated fallback (store E + candidates) ----------------
__global__ void __launch_bounds__(256) k_zero_or_scan(float* __restrict__ out) {
    __shared__ __align__(16) char sm_raw[SMEM_MAIN];

    const int tid  = threadIdx.x;
    const int lane = tid & 31;
    const int wid  = tid >> 5;
    const int wm   = wid >> 2;
    const int wn   = wid & 3;
    const int m0   = blockIdx.y * BM;
    const int n0   = blockIdx.x * BN;
    const uint32_t base = (uint32_t)__cvta_generic_to_shared(sm_raw);

    // always: zero this 128x128 output tile (coalesced float4)
    const float4 z = make_float4(0.f, 0.f, 0.f, 0.f);
#pragma unroll
    for (int it = 0; it < 16; it++) {
        int row = it * 8 + wid;
        *(float4*)&out[(size_t)(m0 + row) * L + n0 + lane * 4] = z;
    }

    if (g_flag == 0) return;   // uniform across grid

    // ---- fallback: recompute sim, store E bf16, capture candidates ----
    float acc[4][4][4];
#pragma unroll
    for (int mi = 0; mi < 4; mi++)
#pragma unroll
        for (int ni = 0; ni < 4; ni++)
#pragma unroll
            for (int j = 0; j < 4; j++) acc[mi][ni][j] = 0.f;

    GEMM_MAINLOOP(acc)

    const int qr = lane >> 2;
    const int qc = lane & 3;
#pragma unroll
    for (int mi = 0; mi < 4; mi++) {
        int gr0 = m0 + wm * 64 + mi * 16 + qr;
        float irs0 = g_invrs[gr0], irs1 = g_invrs[gr0 + 8];
#pragma unroll
        for (int ni = 0; ni < 4; ni++) {
            int gc = n0 + wn * 32 + ni * 8 + qc * 2;
            float ics0 = g_invcs[gc], ics1 = g_invcs[gc + 1];
            __nv_bfloat162 lo = __floats2bfloat162_rn(__expf(acc[mi][ni][0] * SCALE),
                                                      __expf(acc[mi][ni][1] * SCALE));
            __nv_bfloat162 hi = __floats2bfloat162_rn(__expf(acc[mi][ni][2] * SCALE),
                                                      __expf(acc[mi][ni][3] * SCALE));
            *(__nv_bfloat162*)&g_Ebf[(size_t)gr0 * L + gc]       = lo;
            *(__nv_bfloat162*)&g_Ebf[(size_t)(gr0 + 8) * L + gc] = hi;
            float f0 = conf_fn(__bfloat162float(lo.x), irs0, ics0);
            float f1 = conf_fn(__bfloat162float(lo.y), irs0, ics1);
            float f2 = conf_fn(__bfloat162float(hi.x), irs1, ics0);
            float f3 = conf_fn(__bfloat162float(hi.y), irs1, ics1);
            if (f0 > THRESH) { int ix = atomicAdd(&g_ncand, 1); if (ix < CAND_MAX) g_cand[ix] = make_uint4(gr0,     gc,     __float_as_uint(f0), 0); }
            if (f1 > THRESH) { int ix = atomicAdd(&g_ncand, 1); if (ix < CAND_MAX) g_cand[ix] = make_uint4(gr0,     gc + 1, __float_as_uint(f1), 0); }
            if (f2 > THRESH) { int ix = atomicAdd(&g_ncand, 1); if (ix < CAND_MAX) g_cand[ix] = make_uint4(gr0 + 8, gc,     __float_as_uint(f2), 0); }
            if (f3 > THRESH) { int ix = atomicAdd(&g_ncand, 1); if (ix < CAND_MAX) g_cand[ix] = make_uint4(gr0 + 8, gc + 1, __float_as_uint(f3), 0); }
        }
    }
}

// ---------------- pass 3: per-candidate row/col max, write sparse nonzeros ----------------
__global__ void __launch_bounds__(256) k_resolve(float* __restrict__ out) {
    __shared__ float sred[2][8];
    int n = g_ncand;
    if (n > CAND_MAX) n = CAND_MAX;
    const int tid = threadIdx.x, lane = tid & 31, w = tid >> 5;

    for (int ci = blockIdx.x; ci < n; ci += gridDim.x) {
        uint4 cd = g_cand[ci];
        int r = (int)cd.x, c = (int)cd.y;
        unsigned bits = cd.z;
        float irs = g_invrs[r];
        float ics = g_invcs[c];

        float rm = 0.f, cm = 0.f;
        for (int j = tid; j < L; j += 256) {
            rm = fmaxf(rm, conf_fn(__bfloat162float(g_Ebf[(size_t)r * L + j]), irs, g_invcs[j]));
            cm = fmaxf(cm, conf_fn(__bfloat162float(g_Ebf[(size_t)j * L + c]), g_invrs[j], ics));
        }
#pragma unroll
        for (int o = 16; o; o >>= 1) {
            rm = fmaxf(rm, __shfl_xor_sync(0xffffffffu, rm, o));
            cm = fmaxf(cm, __shfl_xor_sync(0xffffffffu, cm, o));
        }
        if (lane == 0) { sred[0][w] = rm; sred[1][w] = cm; }
        __syncthreads();
        if (tid == 0) {
            float rmax = sred[0][0], cmax = sred[1][0];
#pragma unroll
            for (int k = 1; k < 8; k++) {
                rmax = fmaxf(rmax, sred[0][k]);
                cmax = fmaxf(cmax, sred[1][k]);
            }
            if (bits == __float_as_uint(rmax) && bits == __float_as_uint(cmax) &&
                interior(r) && interior(c)) {
                out[(size_t)r * L + c] = __uint_as_float(bits);
            }
        }
        __syncthreads();
    }
}

// ---------------- launch ----------------
extern "C" void kernel_launch(void* const* d_in, const int* in_sizes, int n_in,
                              void* d_out, int out_size) {
    const float* x0 = (const float*)d_in[0];
    const float* x1 = (const float*)d_in[1];
    float* out = (float*)d_out;

    k_convert<<<(L * C / 4 + 255) / 256, 256>>>(x0, x1);

    dim3 grid(L / BN, L / BM);   // 50 x 50
    k_gemm_stats<<<grid, 256>>>();
    k_post<<<(L + 255) / 256, 256>>>();
    k_flag<<<1, 32>>>();
    k_zero_or_scan<<<grid, 256>>>(out);
    k_resolve<<<64, 256>>>(out);
}

// round 14
// speedup vs baseline: 1.8349x; 1.0109x over previous
#include <cuda_runtime.h>
#include <cuda_bf16.h>
#include <cuda_fp8.h>
#include <cstdint>

#define L 6400
#define C 256
#define HW 80
#define MARG 2
#define THRESH 0.2f
// sim = dot / (C * 0.1f)
#define SCALE (1.0f / 25.6f)
#define CAND_MAX 65536

// ---------------- device scratch (no allocations allowed) ----------------
__device__ uint8_t g_A8[L * C];                  // fp8 e4m3 copies
__device__ uint8_t g_B8[L * C];
__device__ __nv_bfloat16 g_Ebf[(size_t)L * L];   // exp(sim) bf16 — written ONLY on fallback
__device__ float g_rowsum[L];
__device__ float g_colsum[L];
__device__ float g_invrs[L];
__device__ float g_invcs[L];
__device__ unsigned g_rsmin;                     // positive-float bits, atomicMin
__device__ unsigned g_csmin;
__device__ unsigned g_simmax_key;                // order-encoded float, atomicMax
__device__ int g_flag;                           // 1 -> candidates possible (fallback)
__device__ int g_ncand;
__device__ uint4 g_cand[CAND_MAX];               // {row, col, conf_bits, pad}

// conf computed bit-identically in fallback-capture and resolve
__device__ __forceinline__ float conf_fn(float e, float irs, float ics) {
    return __fmul_rn(__fmul_rn(e, irs), __fmul_rn(e, ics));
}

__device__ __forceinline__ bool interior(int idx) {
    int i0 = idx / HW;
    int j0 = idx - i0 * HW;
    return ((unsigned)(i0 - MARG) < (unsigned)(HW - 2 * MARG)) &&
           ((unsigned)(j0 - MARG) < (unsigned)(HW - 2 * MARG));
}

// monotone float<->uint encoding (handles negatives) for atomicMax
__device__ __forceinline__ unsigned enc_f(float f) {
    unsigned b = __float_as_uint(f);
    return b ^ ((unsigned)((int)b >> 31) | 0x80000000u);
}
__device__ __forceinline__ float dec_f(unsigned k) {
    unsigned b = (k & 0x80000000u) ? (k ^ 0x80000000u) : ~k;
    return __uint_as_float(b);
}

// ---------------- fp32 -> fp8 conversion (+ init) ----------------
__global__ void k_convert(const float* __restrict__ x0, const float* __restrict__ x1) {
    int i = blockIdx.x * blockDim.x + threadIdx.x;   // over L*C/4
    if (i < L) { g_rowsum[i] = 0.f; g_colsum[i] = 0.f; }
    if (i == 0) {
        g_ncand = 0;
        g_rsmin = 0x7F800000u;   // +inf bits
        g_csmin = 0x7F800000u;
        g_simmax_key = 0u;
    }
    if (i >= L * C / 4) return;
    float4 a = ((const float4*)x0)[i];
    float4 b = ((const float4*)x1)[i];
    unsigned pa = (unsigned)__nv_cvt_float2_to_fp8x2(make_float2(a.x, a.y), __NV_SATFINITE, __NV_E4M3)
                | ((unsigned)__nv_cvt_float2_to_fp8x2(make_float2(a.z, a.w), __NV_SATFINITE, __NV_E4M3) << 16);
    unsigned pb = (unsigned)__nv_cvt_float2_to_fp8x2(make_float2(b.x, b.y), __NV_SATFINITE, __NV_E4M3)
                | ((unsigned)__nv_cvt_float2_to_fp8x2(make_float2(b.z, b.w), __NV_SATFINITE, __NV_E4M3) << 16);
    ((unsigned*)g_A8)[i] = pa;
    ((unsigned*)g_B8)[i] = pb;
}

// ---------------- shared fp8 GEMM mainloop (BM=BN=128, BK=64 bytes) ----------------
#define BM 128
#define BN 128
#define BKB 64      // k-bytes per stage
#define PADB 80     // row stride in bytes (16B aligned, conflict-free ldmatrix)
#define STAGE_B (BM * PADB)            // 10240 B
#define SMEM_MAIN (4 * STAGE_B)        // As[2] + Bs[2] = 40 KB

// computes acc[4][4][4] for this warp's 64x... tile partition
#define GEMM_MAINLOOP(ACC)                                                              \
    {                                                                                   \
        auto as_of = [&](int s_) { return base + (uint32_t)s_ * STAGE_B; };             \
        auto bs_of = [&](int s_) { return base + 2u * STAGE_B + (uint32_t)s_ * STAGE_B; };\
        auto prefetch = [&](int kb, int s_) {                                           \
            _Pragma("unroll")                                                           \
            for (int t = 0; t < 2; t++) {                                               \
                int idx = tid + t * 256;                                                \
                int row = idx >> 2;                                                     \
                int ch  = idx & 3;                                                      \
                uint32_t off = (uint32_t)(row * PADB + ch * 16);                        \
                const void* sa = (const void*)(g_A8 + (size_t)(m0 + row) * C + kb + ch * 16);\
                const void* sb = (const void*)(g_B8 + (size_t)(n0 + row) * C + kb + ch * 16);\
                asm volatile("cp.async.cg.shared.global [%0],[%1],16;\n" :: "r"(as_of(s_) + off), "l"(sa));\
                asm volatile("cp.async.cg.shared.global [%0],[%1],16;\n" :: "r"(bs_of(s_) + off), "l"(sb));\
            }                                                                           \
        };                                                                              \
        prefetch(0, 0);                                                                 \
        asm volatile("cp.async.commit_group;\n");                                       \
        int s = 0;                                                                      \
        for (int kbi = 0; kbi < C / BKB; kbi++) {                                       \
            if (kbi + 1 < C / BKB) {                                                    \
                prefetch((kbi + 1) * BKB, s ^ 1);                                       \
                asm volatile("cp.async.commit_group;\n");                               \
                asm volatile("cp.async.wait_group 1;\n");                               \
            } else {                                                                    \
                asm volatile("cp.async.wait_group 0;\n");                               \
            }                                                                           \
            __syncthreads();                                                            \
            const uint32_t as_base = as_of(s);                                          \
            const uint32_t bs_base = bs_of(s);                                          \
            _Pragma("unroll")                                                           \
            for (int kk = 0; kk < 2; kk++) {                                            \
                uint32_t a[4][4], b[4][2];                                              \
                _Pragma("unroll")                                                       \
                for (int mi = 0; mi < 4; mi++) {                                        \
                    int mrow = wm * 64 + mi * 16 + (lane & 15);                         \
                    int kcol = kk * 32 + ((lane >> 4) << 4);                            \
                    uint32_t addr = as_base + (uint32_t)(mrow * PADB + kcol);           \
                    asm volatile(                                                       \
                        "ldmatrix.sync.aligned.m8n8.x4.shared.b16 {%0,%1,%2,%3},[%4];"  \
                        : "=r"(a[mi][0]), "=r"(a[mi][1]), "=r"(a[mi][2]), "=r"(a[mi][3])\
                        : "r"(addr));                                                   \
                }                                                                       \
                _Pragma("unroll")                                                       \
                for (int p = 0; p < 2; p++) {                                           \
                    int g  = lane >> 3;                                                 \
                    int lr = lane & 7;                                                  \
                    int nrow = wn * 32 + (2 * p + (g >> 1)) * 8 + lr;                   \
                    int kcol = kk * 32 + (g & 1) * 16;                                  \
                    uint32_t addr = bs_base + (uint32_t)(nrow * PADB + kcol);           \
                    asm volatile(                                                       \
                        "ldmatrix.sync.aligned.m8n8.x4.shared.b16 {%0,%1,%2,%3},[%4];"  \
                        : "=r"(b[2 * p][0]), "=r"(b[2 * p][1]),                         \
                          "=r"(b[2 * p + 1][0]), "=r"(b[2 * p + 1][1])                  \
                        : "r"(addr));                                                   \
                }                                                                       \
                _Pragma("unroll")                                                       \
                for (int mi = 0; mi < 4; mi++)                                          \
                    _Pragma("unroll")                                                   \
                    for (int ni = 0; ni < 4; ni++) {                                    \
                        asm volatile(                                                   \
                            "mma.sync.aligned.m16n8k32.row.col.f32.e4m3.e4m3.f32 "      \
                            "{%0,%1,%2,%3},{%4,%5,%6,%7},{%8,%9},{%0,%1,%2,%3};"        \
                            : "+f"(ACC[mi][ni][0]), "+f"(ACC[mi][ni][1]),               \
                              "+f"(ACC[mi][ni][2]), "+f"(ACC[mi][ni][3])                \
                            : "r"(a[mi][0]), "r"(a[mi][1]), "r"(a[mi][2]), "r"(a[mi][3]),\
                              "r"(b[ni][0]), "r"(b[ni][1]));                            \
                    }                                                                   \
            }                                                                           \
            __syncthreads();                                                            \
            s ^= 1;                                                                     \
        }                                                                               \
    }

// ---------------- pass 1: stats GEMM (rowsum/colsum of e, global max sim) ----------------
__global__ void __launch_bounds__(256) k_gemm_stats() {
    __shared__ __align__(16) char sm_raw[SMEM_MAIN];
    __shared__ float srow[BM];
    __shared__ float scol[BN];

    const int tid  = threadIdx.x;
    const int lane = tid & 31;
    const int wid  = tid >> 5;
    const int wm   = wid >> 2;
    const int wn   = wid & 3;
    const int m0   = blockIdx.y * BM;
    const int n0   = blockIdx.x * BN;
    const uint32_t base = (uint32_t)__cvta_generic_to_shared(sm_raw);

    if (tid < BM) { srow[tid] = 0.f; scol[tid] = 0.f; }

    float acc[4][4][4];
#pragma unroll
    for (int mi = 0; mi < 4; mi++)
#pragma unroll
        for (int ni = 0; ni < 4; ni++)
#pragma unroll
            for (int j = 0; j < 4; j++) acc[mi][ni][j] = 0.f;

    GEMM_MAINLOOP(acc)

    // epilogue: e = exp(acc*SCALE); fused row/col sums; global max of sim
    const int qr = lane >> 2;
    const int qc = lane & 3;
    float rowp[4][2], colp[4][2];
#pragma unroll
    for (int i = 0; i < 4; i++) { rowp[i][0] = rowp[i][1] = 0.f; colp[i][0] = colp[i][1] = 0.f; }
    float amax = -1e30f;

#pragma unroll
    for (int mi = 0; mi < 4; mi++) {
#pragma unroll
        for (int ni = 0; ni < 4; ni++) {
            float a0 = acc[mi][ni][0], a1 = acc[mi][ni][1];
            float a2 = acc[mi][ni][2], a3 = acc[mi][ni][3];
            amax = fmaxf(amax, fmaxf(fmaxf(a0, a1), fmaxf(a2, a3)));
            float e0 = __expf(a0 * SCALE);
            float e1 = __expf(a1 * SCALE);
            float e2 = __expf(a2 * SCALE);
            float e3 = __expf(a3 * SCALE);
            rowp[mi][0] += e0 + e1;
            rowp[mi][1] += e2 + e3;
            colp[ni][0] += e0 + e2;
            colp[ni][1] += e1 + e3;
        }
    }
#pragma unroll
    for (int o = 16; o; o >>= 1) amax = fmaxf(amax, __shfl_xor_sync(0xffffffffu, amax, o));
    if (lane == 0) atomicMax(&g_simmax_key, enc_f(amax * SCALE));

#pragma unroll
    for (int mi = 0; mi < 4; mi++)
#pragma unroll
        for (int h = 0; h < 2; h++) {
            float p = rowp[mi][h];
            p += __shfl_xor_sync(0xffffffffu, p, 1);
            p += __shfl_xor_sync(0xffffffffu, p, 2);
            if (qc == 0) atomicAdd(&srow[wm * 64 + mi * 16 + qr + h * 8], p);
        }
#pragma unroll
    for (int ni = 0; ni < 4; ni++)
#pragma unroll
        for (int h = 0; h < 2; h++) {
            float p = colp[ni][h];
            p += __shfl_xor_sync(0xffffffffu, p, 4);
            p += __shfl_xor_sync(0xffffffffu, p, 8);
            p += __shfl_xor_sync(0xffffffffu, p, 16);
            if (qr == 0) atomicAdd(&scol[wn * 32 + ni * 8 + qc * 2 + h], p);
        }
    __syncthreads();
    if (tid < BM) {
        atomicAdd(&g_rowsum[m0 + tid], srow[tid]);
        atomicAdd(&g_colsum[n0 + tid], scol[tid]);
    }
}

// ---------------- recip + global mins ----------------
__global__ void k_post() {
    int i = blockIdx.x * blockDim.x + threadIdx.x;
    if (i < L) {
        float rs = g_rowsum[i], cs = g_colsum[i];
        g_invrs[i] = 1.0f / rs;
        g_invcs[i] = 1.0f / cs;
        atomicMin(&g_rsmin, __float_as_uint(rs));   // positive floats: uint order == float order
        atomicMin(&g_csmin, __float_as_uint(cs));
    }
}

// ---------------- screening flag ----------------
__global__ void k_flag() {
    if (threadIdx.x == 0) {
        float smax  = dec_f(g_simmax_key);
        float rsmin = __uint_as_float(g_rsmin);
        float csmin = __uint_as_float(g_csmin);
        // conf <= exp(2*smax)/(rsmin*csmin); 2.0-nat margin covers fp8/bf16/fp32 discrepancy
        g_flag = (2.f * smax - __logf(rsmin) - __logf(csmin) >= __logf(THRESH) - 2.0f) ? 1 : 0;
    }
}

// ---------------- pass 2: zero output; gated fallback (store E + candidates) ----------------
__global__ void __launch_bounds__(256) k_zero_or_scan(float* __restrict__ out) {
    __shared__ __align__(16) char sm_raw[SMEM_MAIN];

    const int tid  = threadIdx.x;
    const int lane = tid & 31;
    const int wid  = tid >> 5;
    const int wm   = wid >> 2;
    const int wn   = wid & 3;
    const int m0   = blockIdx.y * BM;
    const int n0   = blockIdx.x * BN;
    const uint32_t base = (uint32_t)__cvta_generic_to_shared(sm_raw);

    // always: zero this 128x128 output tile (coalesced float4)
    const float4 z = make_float4(0.f, 0.f, 0.f, 0.f);
#pragma unroll
    for (int it = 0; it < 16; it++) {
        int row = it * 8 + wid;
        *(float4*)&out[(size_t)(m0 + row) * L + n0 + lane * 4] = z;
    }

    if (g_flag == 0) return;   // uniform across grid

    // ---- fallback: recompute sim, store E bf16, capture candidates ----
    float acc[4][4][4];
#pragma unroll
    for (int mi = 0; mi < 4; mi++)
#pragma unroll
        for (int ni = 0; ni < 4; ni++)
#pragma unroll
            for (int j = 0; j < 4; j++) acc[mi][ni][j] = 0.f;

    GEMM_MAINLOOP(acc)

    const int qr = lane >> 2;
    const int qc = lane & 3;
#pragma unroll
    for (int mi = 0; mi < 4; mi++) {
        int gr0 = m0 + wm * 64 + mi * 16 + qr;
        float irs0 = g_invrs[gr0], irs1 = g_invrs[gr0 + 8];
#pragma unroll
        for (int ni = 0; ni < 4; ni++) {
            int gc = n0 + wn * 32 + ni * 8 + qc * 2;
            float ics0 = g_invcs[gc], ics1 = g_invcs[gc + 1];
            __nv_bfloat162 lo = __floats2bfloat162_rn(__expf(acc[mi][ni][0] * SCALE),
                                                      __expf(acc[mi][ni][1] * SCALE));
            __nv_bfloat162 hi = __floats2bfloat162_rn(__expf(acc[mi][ni][2] * SCALE),
                                                      __expf(acc[mi][ni][3] * SCALE));
            *(__nv_bfloat162*)&g_Ebf[(size_t)gr0 * L + gc]       = lo;
            *(__nv_bfloat162*)&g_Ebf[(size_t)(gr0 + 8) * L + gc] = hi;
            float f0 = conf_fn(__bfloat162float(lo.x), irs0, ics0);
            float f1 = conf_fn(__bfloat162float(lo.y), irs0, ics1);
            float f2 = conf_fn(__bfloat162float(hi.x), irs1, ics0);
            float f3 = conf_fn(__bfloat162float(hi.y), irs1, ics1);
            if (f0 > THRESH) { int ix = atomicAdd(&g_ncand, 1); if (ix < CAND_MAX) g_cand[ix] = make_uint4(gr0,     gc,     __float_as_uint(f0), 0); }
            if (f1 > THRESH) { int ix = atomicAdd(&g_ncand, 1); if (ix < CAND_MAX) g_cand[ix] = make_uint4(gr0,     gc + 1, __float_as_uint(f1), 0); }
            if (f2 > THRESH) { int ix = atomicAdd(&g_ncand, 1); if (ix < CAND_MAX) g_cand[ix] = make_uint4(gr0 + 8, gc,     __float_as_uint(f2), 0); }
            if (f3 > THRESH) { int ix = atomicAdd(&g_ncand, 1); if (ix < CAND_MAX) g_cand[ix] = make_uint4(gr0 + 8, gc + 1, __float_as_uint(f3), 0); }
        }
    }
}

// ---------------- pass 3: per-candidate row/col max, write sparse nonzeros ----------------
__global__ void __launch_bounds__(256) k_resolve(float* __restrict__ out) {
    __shared__ float sred[2][8];
    int n = g_ncand;
    if (n > CAND_MAX) n = CAND_MAX;
    const int tid = threadIdx.x, lane = tid & 31, w = tid >> 5;

    for (int ci = blockIdx.x; ci < n; ci += gridDim.x) {
        uint4 cd = g_cand[ci];
        int r = (int)cd.x, c = (int)cd.y;
        unsigned bits = cd.z;
        float irs = g_invrs[r];
        float ics = g_invcs[c];

        float rm = 0.f, cm = 0.f;
        for (int j = tid; j < L; j += 256) {
            rm = fmaxf(rm, conf_fn(__bfloat162float(g_Ebf[(size_t)r * L + j]), irs, g_invcs[j]));
            cm = fmaxf(cm, conf_fn(__bfloat162float(g_Ebf[(size_t)j * L + c]), g_invrs[j], ics));
        }
#pragma unroll
        for (int o = 16; o; o >>= 1) {
            rm = fmaxf(rm, __shfl_xor_sync(0xffffffffu, rm, o));
            cm = fmaxf(cm, __shfl_xor_sync(0xffffffffu, cm, o));
        }
        if (lane == 0) { sred[0][w] = rm; sred[1][w] = cm; }
        __syncthreads();
        if (tid == 0) {
            float rmax = sred[0][0], cmax = sred[1][0];
#pragma unroll
            for (int k = 1; k < 8; k++) {
                rmax = fmaxf(rmax, sred[0][k]);
                cmax = fmaxf(cmax, sred[1][k]);
            }
            if (bits == __float_as_uint(rmax) && bits == __float_as_uint(cmax) &&
                interior(r) && interior(c)) {
                out[(size_t)r * L + c] = __uint_as_float(bits);
            }
        }
        __syncthreads();
    }
}

// ---------------- launch ----------------
extern "C" void kernel_launch(void* const* d_in, const int* in_sizes, int n_in,
                              void* d_out, int out_size) {
    const float* x0 = (const float*)d_in[0];
    const float* x1 = (const float*)d_in[1];
    float* out = (float*)d_out;

    k_convert<<<(L * C / 4 + 255) / 256, 256>>>(x0, x1);

    dim3 grid(L / BN, L / BM);   // 50 x 50
    k_gemm_stats<<<grid, 256>>>();
    k_post<<<(L + 255) / 256, 256>>>();
    k_flag<<<1, 32>>>();
    k_zero_or_scan<<<grid, 256>>>(out);
    k_resolve<<<64, 256>>>(out);
}